// round 1
// baseline (speedup 1.0000x reference)
#include <cuda_runtime.h>
#include <math.h>

#define T_TOK 8192
#define D_DIM 1024
#define H_DIM 684
#define NE 8
#define TM 64
#define TN 64
#define TK 32

// ---- scratch (static device globals: allocation-free per harness rules) ----
__device__ float g_h[(size_t)2 * T_TOK * H_DIM];   // gathered SwiGLU activations [2T, H]
__device__ int   g_rows[2 * T_TOK];                // gathered row -> token id
__device__ float g_comb[2 * T_TOK];                // gathered row -> combine weight
__device__ int   g_cnt[NE];
__device__ int   g_off[NE];
__device__ int   g_cur[NE];
__device__ int   g_top[T_TOK * 2];
__device__ float g_topp[T_TOK * 2];
__device__ int   g_dcnt[NE];                       // top-1 assignment counts
__device__ float g_psum[NE];                       // sum of softmax probs per expert

// ---------------- init: zero output + counters ----------------
__global__ void k_init(float* out, int out_size) {
    int i = blockIdx.x * blockDim.x + threadIdx.x;
    if (i < out_size) out[i] = 0.f;
    if (i < NE) { g_cnt[i] = 0; g_dcnt[i] = 0; g_psum[i] = 0.f; }
}

// ---------------- router: one warp per token ----------------
__global__ void k_router(const float* __restrict__ x, const float* __restrict__ rw) {
    __shared__ float s_ps[NE];
    __shared__ int   s_dc[NE];
    __shared__ int   s_cnt[NE];
    int tid = threadIdx.x;
    if (tid < NE) { s_ps[tid] = 0.f; s_dc[tid] = 0; s_cnt[tid] = 0; }
    __syncthreads();

    int warp = tid >> 5, lane = tid & 31;
    int t = blockIdx.x * 8 + warp;

    // cache the token's row in registers (reused across 8 experts)
    float xv[32];
    const float* xr = x + (size_t)t * D_DIM;
#pragma unroll
    for (int i = 0; i < 32; i++) xv[i] = xr[lane + 32 * i];

    float logit[NE];
#pragma unroll
    for (int e = 0; e < NE; e++) {
        const float* wr = rw + e * D_DIM;
        float s = 0.f;
#pragma unroll
        for (int i = 0; i < 32; i++) s += xv[i] * wr[lane + 32 * i];
#pragma unroll
        for (int o = 16; o; o >>= 1) s += __shfl_xor_sync(0xffffffffu, s, o);
        logit[e] = s;
    }

    if (lane == 0) {
        float mx = logit[0];
#pragma unroll
        for (int e = 1; e < NE; e++) mx = fmaxf(mx, logit[e]);
        float p[NE], sum = 0.f;
#pragma unroll
        for (int e = 0; e < NE; e++) { p[e] = expf(logit[e] - mx); sum += p[e]; }
        float inv = 1.f / sum;
#pragma unroll
        for (int e = 0; e < NE; e++) p[e] *= inv;

        // top-2, first-index-wins on ties (matches jax top_k)
        int i0 = 0;
#pragma unroll
        for (int e = 1; e < NE; e++) if (p[e] > p[i0]) i0 = e;
        int i1 = (i0 == 0) ? 1 : 0;
#pragma unroll
        for (int e = 0; e < NE; e++) if (e != i0 && p[e] > p[i1]) i1 = e;

        g_top[t * 2]     = i0;  g_top[t * 2 + 1]  = i1;
        g_topp[t * 2]    = p[i0]; g_topp[t * 2 + 1] = p[i1];

        atomicAdd(&s_dc[i0], 1);
        atomicAdd(&s_cnt[i0], 1);
        atomicAdd(&s_cnt[i1], 1);
#pragma unroll
        for (int e = 0; e < NE; e++) atomicAdd(&s_ps[e], p[e]);
    }
    __syncthreads();
    if (tid < NE) {
        atomicAdd(&g_psum[tid], s_ps[tid]);
        atomicAdd(&g_dcnt[tid], s_dc[tid]);
        atomicAdd(&g_cnt[tid], s_cnt[tid]);
    }
}

// ---------------- scan offsets + aux loss ----------------
__global__ void k_scan(float* out, int out_size) {
    int o = 0;
    for (int e = 0; e < NE; e++) { g_off[e] = o; g_cur[e] = o; o += g_cnt[e]; }
    float s = 0.f;
    for (int e = 0; e < NE; e++)
        s += ((float)g_dcnt[e] / (float)T_TOK) * (g_psum[e] / (float)T_TOK);
    float aux = 0.01f * s * (float)NE;
    if (out_size > T_TOK * D_DIM) out[T_TOK * D_DIM] = aux;
}

// ---------------- scatter tokens to per-expert contiguous lists ----------------
__global__ void k_scatter() {
    int i = blockIdx.x * blockDim.x + threadIdx.x;  // i = token*2 + slot
    if (i >= T_TOK * 2) return;
    int e = g_top[i];
    int pos = atomicAdd(&g_cur[e], 1);
    g_rows[pos] = i >> 1;
    g_comb[pos] = g_topp[i];
}

// ---------------- GEMM A: h = silu(x@w1^T) * (x@w3^T), gathered rows ----------------
__global__ __launch_bounds__(256) void k_ffn1(const float* __restrict__ x,
                                              const float* __restrict__ w1,
                                              const float* __restrict__ w3) {
    int e = blockIdx.z;
    int cnt = g_cnt[e];
    int m0 = blockIdx.x * TM;
    if (m0 >= cnt) return;
    int base = g_off[e];
    int n0 = blockIdx.y * TN;

    __shared__ float sx[TM][TK + 1];
    __shared__ float sb1[TN][TK + 1];
    __shared__ float sb3[TN][TK + 1];
    __shared__ int   srow[TM];

    int tid = threadIdx.x;
    if (tid < TM) {
        int r = m0 + tid;
        srow[tid] = (r < cnt) ? g_rows[base + r] : -1;
    }
    __syncthreads();

    float acc1[4][4] = {{0}}, acc3[4][4] = {{0}};
    int tx = tid & 15, ty = tid >> 4;
    const float* w1e = w1 + (size_t)e * H_DIM * D_DIM;
    const float* w3e = w3 + (size_t)e * H_DIM * D_DIM;

    for (int k0 = 0; k0 < D_DIM; k0 += TK) {
#pragma unroll
        for (int l = 0; l < 8; l++) {
            int lin = tid + l * 256;
            int r = lin >> 5, k = lin & 31;
            int tok = srow[r];
            sx[r][k] = (tok >= 0) ? x[(size_t)tok * D_DIM + k0 + k] : 0.f;
            int n = n0 + r;
            float v1 = 0.f, v3 = 0.f;
            if (n < H_DIM) {
                v1 = w1e[(size_t)n * D_DIM + k0 + k];
                v3 = w3e[(size_t)n * D_DIM + k0 + k];
            }
            sb1[r][k] = v1; sb3[r][k] = v3;
        }
        __syncthreads();
#pragma unroll
        for (int kk = 0; kk < TK; kk++) {
            float a[4], b1[4], b3[4];
#pragma unroll
            for (int i = 0; i < 4; i++) a[i] = sx[ty * 4 + i][kk];
#pragma unroll
            for (int j = 0; j < 4; j++) { b1[j] = sb1[tx * 4 + j][kk]; b3[j] = sb3[tx * 4 + j][kk]; }
#pragma unroll
            for (int i = 0; i < 4; i++)
#pragma unroll
                for (int j = 0; j < 4; j++) {
                    acc1[i][j] += a[i] * b1[j];
                    acc3[i][j] += a[i] * b3[j];
                }
        }
        __syncthreads();
    }

#pragma unroll
    for (int i = 0; i < 4; i++) {
        int rl = ty * 4 + i;
        int r = m0 + rl;
        if (r >= cnt) continue;
        size_t rowb = (size_t)(base + r) * H_DIM;
#pragma unroll
        for (int j = 0; j < 4; j++) {
            int n = n0 + tx * 4 + j;
            if (n < H_DIM) {
                float h1 = acc1[i][j], h3 = acc3[i][j];
                g_h[rowb + n] = (h1 / (1.f + expf(-h1))) * h3;
            }
        }
    }
}

// ---------------- GEMM B: out += combine * (h @ w2^T) ----------------
__global__ __launch_bounds__(256) void k_ffn2(const float* __restrict__ w2,
                                              float* __restrict__ out) {
    int e = blockIdx.z;
    int cnt = g_cnt[e];
    int m0 = blockIdx.x * TM;
    if (m0 >= cnt) return;
    int base = g_off[e];
    int n0 = blockIdx.y * TN;

    __shared__ float sh[TM][TK + 1];
    __shared__ float sw[TN][TK + 1];
    __shared__ int   srow[TM];
    __shared__ float scomb[TM];

    int tid = threadIdx.x;
    if (tid < TM) {
        int r = m0 + tid;
        srow[tid]  = (r < cnt) ? g_rows[base + r] : 0;
        scomb[tid] = (r < cnt) ? g_comb[base + r] : 0.f;
    }
    __syncthreads();

    float acc[4][4] = {{0}};
    int tx = tid & 15, ty = tid >> 4;
    const float* w2e = w2 + (size_t)e * D_DIM * H_DIM;

    for (int k0 = 0; k0 < H_DIM; k0 += TK) {
#pragma unroll
        for (int l = 0; l < 8; l++) {
            int lin = tid + l * 256;
            int r = lin >> 5, k = lin & 31;
            int kk0 = k0 + k;
            int rr = m0 + r;
            sh[r][k] = (rr < cnt && kk0 < H_DIM) ? g_h[(size_t)(base + rr) * H_DIM + kk0] : 0.f;
            int n = n0 + r;
            sw[r][k] = (kk0 < H_DIM) ? w2e[(size_t)n * H_DIM + kk0] : 0.f;
        }
        __syncthreads();
#pragma unroll
        for (int kk = 0; kk < TK; kk++) {
            float a[4], b[4];
#pragma unroll
            for (int i = 0; i < 4; i++) a[i] = sh[ty * 4 + i][kk];
#pragma unroll
            for (int j = 0; j < 4; j++) b[j] = sw[tx * 4 + j][kk];
#pragma unroll
            for (int i = 0; i < 4; i++)
#pragma unroll
                for (int j = 0; j < 4; j++) acc[i][j] += a[i] * b[j];
        }
        __syncthreads();
    }

#pragma unroll
    for (int i = 0; i < 4; i++) {
        int rl = ty * 4 + i;
        int r = m0 + rl;
        if (r >= cnt) continue;
        int tok = srow[rl];
        float c = scomb[rl];
#pragma unroll
        for (int j = 0; j < 4; j++) {
            int n = n0 + tx * 4 + j;
            atomicAdd(&out[(size_t)tok * D_DIM + n], acc[i][j] * c);
        }
    }
}

extern "C" void kernel_launch(void* const* d_in, const int* in_sizes, int n_in,
                              void* d_out, int out_size) {
    const float* x  = (const float*)d_in[0];
    const float* rw = (const float*)d_in[1];
    const float* w1 = (const float*)d_in[2];
    const float* w2 = (const float*)d_in[3];
    const float* w3 = (const float*)d_in[4];
    float* out = (float*)d_out;

    k_init<<<(out_size + 255) / 256, 256>>>(out, out_size);
    k_router<<<T_TOK / 8, 256>>>(x, rw);
    k_scan<<<1, 1>>>(out, out_size);
    k_scatter<<<(2 * T_TOK + 255) / 256, 256>>>();

    dim3 gA((T_TOK + TM - 1) / TM, (H_DIM + TN - 1) / TN, NE);
    k_ffn1<<<gA, 256>>>(x, w1, w3);
    dim3 gB((T_TOK + TM - 1) / TM, D_DIM / TN, NE);
    k_ffn2<<<gB, 256>>>(w2, out);
}

// round 3
// speedup vs baseline: 3.6348x; 3.6348x over previous
#include <cuda_runtime.h>
#include <cuda_bf16.h>
#include <stdint.h>
#include <math.h>

#define T_TOK 8192
#define TT    16384          // 2*T gathered rows
#define D_DIM 1024
#define H_DIM 684
#define HP    704            // H padded to multiple of 64
#define NE    8
#define K1    3072           // 3*D   (hi | lo | hi)
#define K2    2112           // 3*HP  (hi | lo | hi)

// ======================= scratch =======================
__device__ __nv_bfloat16 xg3[(size_t)TT * K1];
__device__ __nv_bfloat16 w1c[(size_t)NE * H_DIM * K1];
__device__ __nv_bfloat16 w3c[(size_t)NE * H_DIM * K1];
__device__ __nv_bfloat16 w2c[(size_t)NE * D_DIM * K2];
__device__ __nv_bfloat16 h3_[(size_t)TT * K2];
__device__ float g_y[(size_t)TT * D_DIM];

__device__ int   g_rows[TT];
__device__ int   g_pos[TT];
__device__ int   g_cnt[NE];
__device__ int   g_off[NE];
__device__ int   g_cur[NE];
__device__ int   g_top[TT];
__device__ float g_topp[TT];
__device__ int   g_dcnt[NE];
__device__ float g_psum[NE];

// ======================= asm helpers (portable sm_80+) =======================
__device__ __forceinline__ uint32_t smem_to_u32(const void* p) {
    uint32_t a;
    asm("{ .reg .u64 t; cvta.to.shared.u64 t, %1; cvt.u32.u64 %0, t; }" : "=r"(a) : "l"(p));
    return a;
}

__device__ __forceinline__ void cp16(uint32_t dst, const void* src) {
    asm volatile("cp.async.cg.shared.global [%0], [%1], 16;" :: "r"(dst), "l"(src) : "memory");
}
#define CP_COMMIT() asm volatile("cp.async.commit_group;" ::: "memory")
#define CP_WAIT1()  asm volatile("cp.async.wait_group 1;" ::: "memory")

__device__ __forceinline__ void ldsm4(uint32_t* r, uint32_t addr) {
    asm volatile("ldmatrix.sync.aligned.m8n8.x4.shared.b16 {%0,%1,%2,%3}, [%4];"
                 : "=r"(r[0]), "=r"(r[1]), "=r"(r[2]), "=r"(r[3]) : "r"(addr));
}

__device__ __forceinline__ void mma16816(float* c, const uint32_t* a, uint32_t b0, uint32_t b1) {
    asm volatile("mma.sync.aligned.m16n8k16.row.col.f32.bf16.bf16.f32 "
                 "{%0,%1,%2,%3}, {%4,%5,%6,%7}, {%8,%9}, {%0,%1,%2,%3};"
                 : "+f"(c[0]), "+f"(c[1]), "+f"(c[2]), "+f"(c[3])
                 : "r"(a[0]), "r"(a[1]), "r"(a[2]), "r"(a[3]), "r"(b0), "r"(b1));
}

// ======================= small kernels =======================
__global__ void k_init0() {
    int i = threadIdx.x;
    if (i < NE) { g_cnt[i] = 0; g_dcnt[i] = 0; g_psum[i] = 0.f; }
}

__global__ void k_router(const float* __restrict__ x, const float* __restrict__ rw) {
    __shared__ float s_ps[NE];
    __shared__ int   s_dc[NE];
    __shared__ int   s_cnt[NE];
    int tid = threadIdx.x;
    if (tid < NE) { s_ps[tid] = 0.f; s_dc[tid] = 0; s_cnt[tid] = 0; }
    __syncthreads();

    int warp = tid >> 5, lane = tid & 31;
    int t = blockIdx.x * 8 + warp;

    float xv[32];
    const float* xr = x + (size_t)t * D_DIM;
#pragma unroll
    for (int i = 0; i < 32; i++) xv[i] = xr[lane + 32 * i];

    float logit[NE];
#pragma unroll
    for (int e = 0; e < NE; e++) {
        const float* wr = rw + e * D_DIM;
        float s = 0.f;
#pragma unroll
        for (int i = 0; i < 32; i++) s += xv[i] * wr[lane + 32 * i];
#pragma unroll
        for (int o = 16; o; o >>= 1) s += __shfl_xor_sync(0xffffffffu, s, o);
        logit[e] = s;
    }

    if (lane == 0) {
        float mx = logit[0];
#pragma unroll
        for (int e = 1; e < NE; e++) mx = fmaxf(mx, logit[e]);
        float p[NE], sum = 0.f;
#pragma unroll
        for (int e = 0; e < NE; e++) { p[e] = expf(logit[e] - mx); sum += p[e]; }
        float inv = 1.f / sum;
#pragma unroll
        for (int e = 0; e < NE; e++) p[e] *= inv;

        int i0 = 0;
#pragma unroll
        for (int e = 1; e < NE; e++) if (p[e] > p[i0]) i0 = e;
        int i1 = (i0 == 0) ? 1 : 0;
#pragma unroll
        for (int e = 0; e < NE; e++) if (e != i0 && p[e] > p[i1]) i1 = e;

        g_top[t * 2]      = i0;    g_top[t * 2 + 1]  = i1;
        g_topp[t * 2]     = p[i0]; g_topp[t * 2 + 1] = p[i1];

        atomicAdd(&s_dc[i0], 1);
        atomicAdd(&s_cnt[i0], 1);
        atomicAdd(&s_cnt[i1], 1);
#pragma unroll
        for (int e = 0; e < NE; e++) atomicAdd(&s_ps[e], p[e]);
    }
    __syncthreads();
    if (tid < NE) {
        atomicAdd(&g_psum[tid], s_ps[tid]);
        atomicAdd(&g_dcnt[tid], s_dc[tid]);
        atomicAdd(&g_cnt[tid], s_cnt[tid]);
    }
}

__global__ void k_scan(float* out, int out_size) {
    int o = 0;
    for (int e = 0; e < NE; e++) { g_off[e] = o; g_cur[e] = o; o += g_cnt[e]; }
    float s = 0.f;
    for (int e = 0; e < NE; e++)
        s += ((float)g_dcnt[e] / (float)T_TOK) * (g_psum[e] / (float)T_TOK);
    float aux = 0.01f * s * (float)NE;
    if (out_size > T_TOK * D_DIM) out[T_TOK * D_DIM] = aux;
}

__global__ void k_scatter() {
    int i = blockIdx.x * blockDim.x + threadIdx.x;
    if (i >= TT) return;
    int e = g_top[i];
    int pos = atomicAdd(&g_cur[e], 1);
    g_rows[pos] = i >> 1;
    g_pos[i] = pos;
}

// ---- bf16 hi/lo split ----
__device__ __forceinline__ void bsplit(float v, __nv_bfloat16& h, __nv_bfloat16& l) {
    h = __float2bfloat16(v);
    l = __float2bfloat16(v - __bfloat162float(h));
}
// store float4 v split: hi at base+o, lo at base+o+seg, hi dup at base+o+2*seg
__device__ __forceinline__ void store4_3seg(__nv_bfloat16* base, size_t o, size_t seg, float4 v) {
    __nv_bfloat16 h0,l0,h1,l1,h2,l2,h3,l3;
    bsplit(v.x,h0,l0); bsplit(v.y,h1,l1); bsplit(v.z,h2,l2); bsplit(v.w,h3,l3);
    __nv_bfloat162 ha; ha.x=h0; ha.y=h1;
    __nv_bfloat162 hb; hb.x=h2; hb.y=h3;
    __nv_bfloat162 la; la.x=l0; la.y=l1;
    __nv_bfloat162 lb; lb.x=l2; lb.y=l3;
    *reinterpret_cast<__nv_bfloat162*>(base + o)           = ha;
    *reinterpret_cast<__nv_bfloat162*>(base + o + 2)       = hb;
    *reinterpret_cast<__nv_bfloat162*>(base + o + seg)     = la;
    *reinterpret_cast<__nv_bfloat162*>(base + o + seg + 2) = lb;
    *reinterpret_cast<__nv_bfloat162*>(base + o + 2*seg)     = ha;
    *reinterpret_cast<__nv_bfloat162*>(base + o + 2*seg + 2) = hb;
}

// weights: rows of 1024 -> K1 rows, layout [hi | hi | lo] (swap lo/hi-dup segments)
__device__ __forceinline__ void store4_w(__nv_bfloat16* base, size_t o, size_t seg, float4 v) {
    __nv_bfloat16 h0,l0,h1,l1,h2,l2,h3,l3;
    bsplit(v.x,h0,l0); bsplit(v.y,h1,l1); bsplit(v.z,h2,l2); bsplit(v.w,h3,l3);
    __nv_bfloat162 ha; ha.x=h0; ha.y=h1;
    __nv_bfloat162 hb; hb.x=h2; hb.y=h3;
    __nv_bfloat162 la; la.x=l0; la.y=l1;
    __nv_bfloat162 lb; lb.x=l2; lb.y=l3;
    *reinterpret_cast<__nv_bfloat162*>(base + o)           = ha;
    *reinterpret_cast<__nv_bfloat162*>(base + o + 2)       = hb;
    *reinterpret_cast<__nv_bfloat162*>(base + o + seg)     = ha;
    *reinterpret_cast<__nv_bfloat162*>(base + o + seg + 2) = hb;
    *reinterpret_cast<__nv_bfloat162*>(base + o + 2*seg)     = la;
    *reinterpret_cast<__nv_bfloat162*>(base + o + 2*seg + 2) = lb;
}

// w1,w3: [NE*H][1024] -> [NE*H][3072]  A'=[xh|xl|xh] pairs with B'=[wh|wh|wl]
__global__ void k_conv13(const float* __restrict__ w1, const float* __restrict__ w3) {
    size_t i = (size_t)blockIdx.x * 256 + threadIdx.x;     // float4 index over [NE*H][256]
    size_t row = i >> 8;
    size_t col = (i & 255) * 4;
    float4 a = reinterpret_cast<const float4*>(w1)[i];
    float4 b = reinterpret_cast<const float4*>(w3)[i];
    store4_w(w1c, row * K1 + col, D_DIM, a);
    store4_w(w3c, row * K1 + col, D_DIM, b);
}

// w2: [NE*D][684] -> [NE*D][2112] with K padded to 704, layout [hi|hi|lo]
__global__ void k_conv2(const float* __restrict__ w2) {
    size_t i = (size_t)blockIdx.x * 256 + threadIdx.x;     // over [NE*D][176] float4s
    size_t row = i / 176;
    int col = (int)(i % 176) * 4;
    float4 v = make_float4(0.f, 0.f, 0.f, 0.f);
    if (col < H_DIM) {
        const float* p = w2 + row * H_DIM + col;
        v.x = p[0];
        v.y = (col + 1 < H_DIM) ? p[1] : 0.f;
        v.z = (col + 2 < H_DIM) ? p[2] : 0.f;
        v.w = (col + 3 < H_DIM) ? p[3] : 0.f;
    }
    store4_w(w2c, row * K2 + (size_t)col, HP, v);
}

// gather x rows -> xg3 [hi | lo | hi]
__global__ void k_gather(const float* __restrict__ x) {
    int p = blockIdx.x, c = threadIdx.x;
    int tok = g_rows[p];
    float4 v = reinterpret_cast<const float4*>(x)[(size_t)tok * 256 + c];
    store4_3seg(xg3, (size_t)p * K1 + (size_t)c * 4, D_DIM, v);
}

__global__ void k_combine(float* __restrict__ out) {
    int i = blockIdx.x * 256 + threadIdx.x;
    int t = i >> 8, c = i & 255;
    int p0 = g_pos[2 * t], p1 = g_pos[2 * t + 1];
    float c0 = g_topp[2 * t], c1 = g_topp[2 * t + 1];
    const float4* y = reinterpret_cast<const float4*>(g_y);
    float4 a = y[(size_t)p0 * 256 + c];
    float4 b = y[(size_t)p1 * 256 + c];
    float4 o;
    o.x = c0 * a.x + c1 * b.x;  o.y = c0 * a.y + c1 * b.y;
    o.z = c0 * a.z + c1 * b.z;  o.w = c0 * a.w + c1 * b.w;
    reinterpret_cast<float4*>(out)[(size_t)t * 256 + c] = o;
}

// ======================= GEMM cores =======================
// smem tile: 128 rows x 32 bf16, row stride 40 bf16 (80B) -> conflict-free ldmatrix
#define TILE_B   10240     // 128*80
#define RSTRIDE  80

__device__ __forceinline__ void compute_warp(
    uint32_t sA, uint32_t sB, const uint32_t a[2][2][4],
    float acc[2][4][4], int warp_n0, int lane)
{
#pragma unroll
    for (int nj2 = 0; nj2 < 2; nj2++) {
#pragma unroll
        for (int kh = 0; kh < 2; kh++) {
            uint32_t r[4];
            uint32_t bd = sB + (warp_n0 + nj2*16 + (lane & 15)) * RSTRIDE
                             + (kh*16 + (lane >> 4) * 8) * 2;
            ldsm4(r, bd);
            mma16816(acc[0][nj2*2 + 0], a[0][kh], r[0], r[2]);
            mma16816(acc[0][nj2*2 + 1], a[0][kh], r[1], r[3]);
            mma16816(acc[1][nj2*2 + 0], a[1][kh], r[0], r[2]);
            mma16816(acc[1][nj2*2 + 1], a[1][kh], r[1], r[3]);
        }
    }
}

__device__ __forceinline__ void load_a_frags(
    uint32_t sA, uint32_t a[2][2][4], int warp_m0, int lane)
{
#pragma unroll
    for (int mi = 0; mi < 2; mi++)
#pragma unroll
        for (int kh = 0; kh < 2; kh++) {
            uint32_t ad = sA + (warp_m0 + mi*16 + (lane & 15)) * RSTRIDE
                             + (kh*16 + (lane >> 4) * 8) * 2;
            ldsm4(a[mi][kh], ad);
        }
}

// ------- GEMM1: h3 = split( swiglu(xg3 @ w1c^T, xg3 @ w3c^T) ) -------
__global__ __launch_bounds__(512, 1) void k_gemm1() {
    extern __shared__ char smem[];
    const int e = blockIdx.z;
    const int cnt = g_cnt[e];
    const int m0 = blockIdx.x * 128;
    if (m0 >= cnt) return;
    const int base = g_off[e];
    const int n0g = blockIdx.y * 128;
    const int tid = threadIdx.x, wid = tid >> 5, lane = tid & 31;
    const int warp_m0 = (wid >> 2) * 32, warp_n0 = (wid & 3) * 32;

    uint32_t sb = smem_to_u32(smem);
    const __nv_bfloat16* B1 = w1c + (size_t)e * H_DIM * K1;
    const __nv_bfloat16* B3 = w3c + (size_t)e * H_DIM * K1;
    const long arow = base + m0;
    const int lrow = tid >> 2, lch = tid & 3;        // 512 thr -> 128 rows x 4 chunks

    long ar = arow + lrow; if (ar >= TT) ar = TT - 1;
    int nr = n0g + lrow;  if (nr > H_DIM - 1) nr = H_DIM - 1;
    const __nv_bfloat16* gA  = xg3 + ar * (long)K1 + lch * 8;
    const __nv_bfloat16* gB1 = B1 + (long)nr * K1 + lch * 8;
    const __nv_bfloat16* gB3 = B3 + (long)nr * K1 + lch * 8;
    const uint32_t sdst = sb + lrow * RSTRIDE + lch * 16;

    auto load_stage = [&](int st, int c) {
        long k0 = (long)c * 32;
        uint32_t d = sdst + st * (3 * TILE_B);
        cp16(d,              gA  + k0);
        cp16(d + TILE_B,     gB1 + k0);
        cp16(d + 2*TILE_B,   gB3 + k0);
    };

    float acc1[2][4][4] = {{{0}}}, acc3[2][4][4] = {{{0}}};

    load_stage(0, 0); CP_COMMIT();
    load_stage(1, 1); CP_COMMIT();

    const int NC = K1 / 32;   // 96
    for (int c = 0; c < NC; c++) {
        CP_WAIT1();
        __syncthreads();
        if (c + 2 < NC) load_stage((c + 2) % 3, c + 2);
        CP_COMMIT();
        uint32_t sA = sb + (c % 3) * (3 * TILE_B);
        uint32_t a[2][2][4];
        load_a_frags(sA, a, warp_m0, lane);
        compute_warp(sA, sA + TILE_B,   a, acc1, warp_n0, lane);
        compute_warp(sA, sA + 2*TILE_B, a, acc3, warp_n0, lane);
        __syncthreads();
    }

    // epilogue: swiglu + re-split into h3 [hi | lo | hi]
#pragma unroll
    for (int mi = 0; mi < 2; mi++) {
#pragma unroll
        for (int nj = 0; nj < 4; nj++) {
            int n = n0g + warp_n0 + nj * 8 + ((lane & 3) << 1);
            if (n >= HP) continue;
            bool live = (n < H_DIM);
#pragma unroll
            for (int h = 0; h < 2; h++) {
                int rl = warp_m0 + mi * 16 + (lane >> 2) + h * 8;
                int r = m0 + rl;
                if (r >= cnt) continue;
                float v1a = acc1[mi][nj][2*h],   v3a = acc3[mi][nj][2*h];
                float v1b = acc1[mi][nj][2*h+1], v3b = acc3[mi][nj][2*h+1];
                float ha = live ? (v1a / (1.f + __expf(-v1a))) * v3a : 0.f;
                float hb = live ? (v1b / (1.f + __expf(-v1b))) * v3b : 0.f;
                __nv_bfloat16 hah, hal, hbh, hbl;
                bsplit(ha, hah, hal); bsplit(hb, hbh, hbl);
                __nv_bfloat162 hv; hv.x = hah; hv.y = hbh;
                __nv_bfloat162 lv; lv.x = hal; lv.y = hbl;
                size_t rb = (size_t)(base + r) * K2;
                *reinterpret_cast<__nv_bfloat162*>(h3_ + rb + n)          = hv;
                *reinterpret_cast<__nv_bfloat162*>(h3_ + rb + HP + n)     = lv;
                *reinterpret_cast<__nv_bfloat162*>(h3_ + rb + 2*HP + n)   = hv;
            }
        }
    }
}

// ------- GEMM2: y = h3 @ w2c^T -------
__global__ __launch_bounds__(512, 1) void k_gemm2() {
    extern __shared__ char smem[];
    const int e = blockIdx.z;
    const int cnt = g_cnt[e];
    const int m0 = blockIdx.x * 128;
    if (m0 >= cnt) return;
    const int base = g_off[e];
    const int n0g = blockIdx.y * 128;
    const int tid = threadIdx.x, wid = tid >> 5, lane = tid & 31;
    const int warp_m0 = (wid >> 2) * 32, warp_n0 = (wid & 3) * 32;

    uint32_t sb = smem_to_u32(smem);
    const __nv_bfloat16* B = w2c + (size_t)e * D_DIM * K2;
    const long arow = base + m0;
    const int lrow = tid >> 2, lch = tid & 3;

    long ar = arow + lrow; if (ar >= TT) ar = TT - 1;
    int nr = n0g + lrow;                       // < 1024 always
    const __nv_bfloat16* gA = h3_ + ar * (long)K2 + lch * 8;
    const __nv_bfloat16* gB = B + (long)nr * K2 + lch * 8;
    const uint32_t sdst = sb + lrow * RSTRIDE + lch * 16;

    auto load_stage = [&](int st, int c) {
        long k0 = (long)c * 32;
        uint32_t d = sdst + st * (2 * TILE_B);
        cp16(d,          gA + k0);
        cp16(d + TILE_B, gB + k0);
    };

    float acc[2][4][4] = {{{0}}};

    load_stage(0, 0); CP_COMMIT();
    load_stage(1, 1); CP_COMMIT();

    const int NC = K2 / 32;   // 66
    for (int c = 0; c < NC; c++) {
        CP_WAIT1();
        __syncthreads();
        if (c + 2 < NC) load_stage((c + 2) % 3, c + 2);
        CP_COMMIT();
        uint32_t sA = sb + (c % 3) * (2 * TILE_B);
        uint32_t a[2][2][4];
        load_a_frags(sA, a, warp_m0, lane);
        compute_warp(sA, sA + TILE_B, a, acc, warp_n0, lane);
        __syncthreads();
    }

#pragma unroll
    for (int mi = 0; mi < 2; mi++) {
#pragma unroll
        for (int nj = 0; nj < 4; nj++) {
            int n = n0g + warp_n0 + nj * 8 + ((lane & 3) << 1);
#pragma unroll
            for (int h = 0; h < 2; h++) {
                int rl = warp_m0 + mi * 16 + (lane >> 2) + h * 8;
                int r = m0 + rl;
                if (r >= cnt) continue;
                float2 v; v.x = acc[mi][nj][2*h]; v.y = acc[mi][nj][2*h+1];
                *reinterpret_cast<float2*>(g_y + (size_t)(base + r) * D_DIM + n) = v;
            }
        }
    }
}

// ======================= launch =======================
extern "C" void kernel_launch(void* const* d_in, const int* in_sizes, int n_in,
                              void* d_out, int out_size) {
    const float* x  = (const float*)d_in[0];
    const float* rw = (const float*)d_in[1];
    const float* w1 = (const float*)d_in[2];
    const float* w2 = (const float*)d_in[3];
    const float* w3 = (const float*)d_in[4];
    float* out = (float*)d_out;

    cudaFuncSetAttribute(k_gemm1, cudaFuncAttributeMaxDynamicSharedMemorySize, 3 * 3 * TILE_B);
    cudaFuncSetAttribute(k_gemm2, cudaFuncAttributeMaxDynamicSharedMemorySize, 3 * 2 * TILE_B);

    k_init0<<<1, 32>>>();
    k_router<<<T_TOK / 8, 256>>>(x, rw);
    k_scan<<<1, 1>>>(out, out_size);
    k_scatter<<<TT / 256, 256>>>();

    k_conv13<<<NE * H_DIM, 256>>>(w1, w3);       // 5472 blocks
    k_conv2<<<NE * D_DIM * 176 / 256, 256>>>(w2);// 5632 blocks
    k_gather<<<TT, 256>>>(x);

    k_gemm1<<<dim3(64, 6, 8), 512, 3 * 3 * TILE_B>>>();
    k_gemm2<<<dim3(64, 8, 8), 512, 3 * 2 * TILE_B>>>();
    k_combine<<<T_TOK, 256>>>(out);
}